// round 14
// baseline (speedup 1.0000x reference)
#include <cuda_runtime.h>

// Problem: B=1, L=768, D_SINGLE=384, D_PAIR=128
//   left  = s @ W[:384] + bias   (768x128)   [bias folded into left]
//   right = s @ W[384:]          (768x128)
//   out[i,j,f] = left[i,f] + right[j,f]      -> 768*768*128 fp32 = 302 MB
//
// R14 = R5 champion with ONE change: bcast stores widened to 256-bit
// st.global.cs.v8.b32 (evict-first policy preserved). 16 threads cover one
// 512B j-row; each warp writes 2 consecutive rows per step; 8 warps cover 16
// consecutive rows = contiguous 8KB write front per iteration. Store
// instruction count halved. Everything else byte-identical to the champion.
//
// Inputs (metadata order): s (768*384 f32), z (UNUSED), W (768*128 f32), bias (128 f32)

#define L_DIM 768
#define DS 384
#define DP 128
#define TI 6          // rows per proj block -> 128 blocks (single wave)

// scratch (no cudaMalloc allowed)
__device__ float g_left[L_DIM * DP];    // includes bias
__device__ float g_right[L_DIM * DP];

// ---------------------------------------------------------------------------
// Kernel 1: projections. 128 blocks x 256 threads. (champion, unchanged)
// ---------------------------------------------------------------------------
__global__ __launch_bounds__(256) void proj_kernel(
    const float* __restrict__ s,     // [768, 384]
    const float* __restrict__ W,     // [768, 128]
    const float* __restrict__ bias)  // [128]
{
    __shared__ float s_sh[TI][DS];
    const int i0  = blockIdx.x * TI;
    const int tid = threadIdx.x;

    for (int idx = tid; idx < TI * DS; idx += 256) {
        int r = idx / DS, c = idx % DS;
        s_sh[r][c] = s[(size_t)(i0 + r) * DS + c];
    }
    __syncthreads();

    const int f    = tid & 127;
    const int half = tid >> 7;                    // 0 = left, 1 = right
    const float* Wcol = W + (size_t)(half ? DS : 0) * DP + f;

    float acc[TI];
#pragma unroll
    for (int ii = 0; ii < TI; ii++) acc[ii] = 0.f;

    const float4 (*s4)[DS / 4] = reinterpret_cast<const float4 (*)[DS / 4]>(s_sh);

#pragma unroll 4
    for (int k4 = 0; k4 < DS / 4; k4++) {
        const int kb = k4 * 4;
        float w0 = Wcol[(size_t)(kb + 0) * DP];
        float w1 = Wcol[(size_t)(kb + 1) * DP];
        float w2 = Wcol[(size_t)(kb + 2) * DP];
        float w3 = Wcol[(size_t)(kb + 3) * DP];
#pragma unroll
        for (int ii = 0; ii < TI; ii++) {
            float4 sv = s4[ii][k4];               // one LDS.128, warp-broadcast
            acc[ii] = fmaf(sv.x, w0, acc[ii]);
            acc[ii] = fmaf(sv.y, w1, acc[ii]);
            acc[ii] = fmaf(sv.z, w2, acc[ii]);
            acc[ii] = fmaf(sv.w, w3, acc[ii]);
        }
    }

    if (half == 0) {
        const float b = bias[f];
#pragma unroll
        for (int ii = 0; ii < TI; ii++)
            g_left[(size_t)(i0 + ii) * DP + f] = acc[ii] + b;
    } else {
#pragma unroll
        for (int ii = 0; ii < TI; ii++)
            g_right[(size_t)(i0 + ii) * DP + f] = acc[ii];
    }

    __syncthreads();
    __threadfence();
    cudaTriggerProgrammaticLaunchCompletion();
}

// ---------------------------------------------------------------------------
// 256-bit evict-first (streaming) store
// ---------------------------------------------------------------------------
__device__ __forceinline__ void stcs256(void* p, float4 a, float4 b) {
    asm volatile(
        "st.global.cs.v8.b32 [%0], {%1,%2,%3,%4,%5,%6,%7,%8};"
        :: "l"(p),
           "r"(__float_as_uint(a.x)), "r"(__float_as_uint(a.y)),
           "r"(__float_as_uint(a.z)), "r"(__float_as_uint(a.w)),
           "r"(__float_as_uint(b.x)), "r"(__float_as_uint(b.y)),
           "r"(__float_as_uint(b.z)), "r"(__float_as_uint(b.w))
        : "memory");
}

// ---------------------------------------------------------------------------
// Kernel 2: broadcast-add with 256-bit streaming stores.
// grid = (6 j-chunks, 768 i). 256 threads: f8 = tid&15 (8 floats each),
// jl = tid>>4 (16 parallel j rows). Per step: 16 consecutive rows = 8KB.
// ---------------------------------------------------------------------------
__global__ __launch_bounds__(256) void bcast_kernel(float* __restrict__ out)
{
    const int i   = blockIdx.y;
    const int j0  = blockIdx.x * 128;
    const int tid = threadIdx.x;
    const int f8  = tid & 15;          // 8-float (32B) group within the row
    const int jl  = tid >> 4;          // 0..15

    cudaGridDependencySynchronize();   // PDL: wait for proj's triggered stores

    const float4* left4  = reinterpret_cast<const float4*>(g_left);
    const float4* right4 = reinterpret_cast<const float4*>(g_right);
    float4* out4 = reinterpret_cast<float4*>(out);

    const float4 lv0 = left4[(size_t)i * 32 + f8 * 2 + 0];   // includes bias
    const float4 lv1 = left4[(size_t)i * 32 + f8 * 2 + 1];
    const size_t orow = ((size_t)i * L_DIM + j0) * 32 + f8 * 2;

#pragma unroll 4
    for (int jj = jl; jj < 128; jj += 16) {
        float4 r0 = __ldg(right4 + (size_t)(j0 + jj) * 32 + f8 * 2 + 0);
        float4 r1 = __ldg(right4 + (size_t)(j0 + jj) * 32 + f8 * 2 + 1);
        float4 a, b;
        a.x = lv0.x + r0.x;  a.y = lv0.y + r0.y;
        a.z = lv0.z + r0.z;  a.w = lv0.w + r0.w;
        b.x = lv1.x + r1.x;  b.y = lv1.y + r1.y;
        b.z = lv1.z + r1.z;  b.w = lv1.w + r1.w;
        stcs256(out4 + orow + (size_t)jj * 32, a, b);   // one 32B streaming store
    }
}

// ---------------------------------------------------------------------------
extern "C" void kernel_launch(void* const* d_in, const int* in_sizes, int n_in,
                              void* d_out, int out_size)
{
    const float* s    = (const float*)d_in[0];
    // d_in[1] = z : intentionally unused (reference never reads it)
    const float* W    = (const float*)d_in[2];
    const float* bias = (const float*)d_in[3];
    float* out = (float*)d_out;

    proj_kernel<<<L_DIM / TI, 256>>>(s, W, bias);

    cudaLaunchConfig_t cfg = {};
    cfg.gridDim  = dim3(L_DIM / 128, L_DIM);   // (6, 768)
    cfg.blockDim = dim3(256, 1, 1);
    cfg.dynamicSmemBytes = 0;
    cfg.stream = 0;

    cudaLaunchAttribute attr;
    attr.id = cudaLaunchAttributeProgrammaticStreamSerialization;
    attr.val.programmaticStreamSerializationAllowed = 1;
    cfg.attrs = &attr;
    cfg.numAttrs = 1;

    cudaLaunchKernelEx(&cfg, bcast_kernel, out);
}